// round 13
// baseline (speedup 1.0000x reference)
#include <cuda_runtime.h>
#include <math.h>
#include <stdint.h>

// ---------------- problem constants ----------------
#define Nn      129
#define Fdim    262144
#define Ee      16384
#define GRID    148
#define NTHR    1024
#define NCOPY   8
#define PADS    64                      // 256B stride between accumulator slots
#define XPAD    32                      // 128B stride for xw accumulators
#define NSLOT   (3 * Nn)                // 387 (ch,node) slots
#define PART2   16                      // blocks in post-dot phases

// ---- TMA side: rows 0..111 (28 quads) — hot, stays L2-resident across replays ----
#define NQUADT  28
#define NJOBST  (NQUADT * 16)           // 448 jobs: (quad, 64KB chunk)
#define STGF    2048                    // floats per row-slice per stage (8KB)
#define STGB    8192u
#define SLOTB   (5u * STGB)             // 40KB per slot
#define NSLOTS  4                       // ring depth -> 160KB dynamic smem

// ---- LDG side: rows 112..128 streamed evict-first (cold) ----
#define LROW0   112
#define LROWS   17
#define LTILES  (LROWS * 64)            // 1088 tiles of 16KB
#define LWARPS  15
#define TOTLW   (GRID * LWARPS)

// ---------------- device scratch ----------------
__device__ float    g_xwa[Nn * XPAD];
__device__ float    g_deg[NSLOT * PADS];
__device__ float    g_h1 [NCOPY * NSLOT * PADS];
__device__ float    g_h2 [NCOPY * NSLOT * PADS];
__device__ unsigned g_bar[4];

__device__ __forceinline__ void gridbar(int k, unsigned cnt) {
    __syncthreads();
    __threadfence();
    if (threadIdx.x == 0) {
        unsigned v = atomicAdd(&g_bar[k], 1u);
        unsigned target = (v / cnt) * cnt + cnt;
        while (atomicAdd(&g_bar[k], 0u) < target) __nanosleep(32);
    }
    __syncthreads();
    __threadfence();
}

__device__ __forceinline__ float eluf(float a) { return a > 0.f ? a : expm1f(a); }

__device__ __forceinline__ uint32_t smem_u32(const void* p) {
    uint32_t a;
    asm("{ .reg .u64 tmp; cvta.to.shared.u64 tmp, %1; cvt.u32.u64 %0, tmp; }"
        : "=r"(a) : "l"(p));
    return a;
}
__device__ __forceinline__ void mbar_init(uint32_t mbar, uint32_t cnt) {
    asm volatile("mbarrier.init.shared.b64 [%0], %1;" :: "r"(mbar), "r"(cnt) : "memory");
}
__device__ __forceinline__ void mbar_wait(uint32_t mbar, uint32_t parity) {
    asm volatile(
        "{\n\t.reg .pred P;\n\t"
        "WL_%=:\n\t"
        "mbarrier.try_wait.parity.acquire.cta.shared::cta.b64 P, [%0], %1, 0x989680;\n\t"
        "@P bra WD_%=;\n\tbra WL_%=;\n\tWD_%=:\n\t}"
        :: "r"(mbar), "r"(parity) : "memory");
}

#define BULK(dst, src) \
    asm volatile("cp.async.bulk.shared::cluster.global.mbarrier::complete_tx::bytes [%0], [%1], %2, [%3];" \
                 :: "r"(dst), "l"(src), "r"(STGB), "r"(mbar) : "memory")

// producer: one 40KB stage (4 x-row slices of rows 4q.. + w slice)
__device__ __forceinline__ void issue_stage(int j0, int k,
                                            const float* __restrict__ x,
                                            const float* __restrict__ w,
                                            uint32_t dyn0, uint32_t mbar_base) {
    const int job  = j0 + (k >> 3);
    const int s    = k & 7;
    const int quad = job >> 4, chunk = job & 15;
    const size_t base = (size_t)chunk * 16384 + (size_t)s * STGF;
    const int slot = k & 3;
    const uint32_t dst  = dyn0 + (uint32_t)slot * SLOTB;
    const uint32_t mbar = mbar_base + slot * 8u;
    asm volatile("mbarrier.arrive.expect_tx.shared.b64 _, [%0], %1;"
                 :: "r"(mbar), "r"(SLOTB) : "memory");
#pragma unroll
    for (int i = 0; i < 4; i++)
        BULK(dst + (uint32_t)i * STGB, x + (size_t)(4 * quad + i) * Fdim + base);
    BULK(dst + 4u * STGB, w + base);
}

__global__ void __launch_bounds__(NTHR, 1)
dgcnn_fused(const float* __restrict__ x,   const float* __restrict__ w,
            const int*   __restrict__ ei,  const float* __restrict__ ea,
            const float* __restrict__ g1b, const float* __restrict__ g2W,
            const float* __restrict__ g2b,
            const float* __restrict__ c1w, const float* __restrict__ c1b,
            const float* __restrict__ c2w, const float* __restrict__ c2b,
            const float* __restrict__ f1W, const float* __restrict__ f1b,
            const float* __restrict__ f2W, const float* __restrict__ f2b,
            const float* __restrict__ f3W, const float* __restrict__ f3b,
            float* __restrict__ out) {
    extern __shared__ float4 dsm[];               // 4 x 40KB TMA ring
    __shared__ uint64_t mbarArr[NSLOTS];
    __shared__ float sredf[64];
    __shared__ float s_xw[Nn], s_dinv[NSLOT], s_h1f[NSLOT], s_h2a[NSLOT];
    __shared__ float z0[NSLOT], z1[NSLOT];
    __shared__ float c1s[3 * 3 * 127], p1s[3 * 3 * 125], c2s[3 * 123];
    __shared__ float allx[363], f1s[32], f2s[6];

    const int t    = threadIdx.x;
    const int bid  = blockIdx.x;
    const int lane = t & 31, warp = t >> 5;

    const uint32_t dyn0      = smem_u32(dsm);
    const uint32_t mbar_base = smem_u32(mbarArr);

    const int j0 = (bid * NJOBST) / GRID;
    const int j1 = ((bid + 1) * NJOBST) / GRID;
    const int T  = (j1 - j0) * 8;                 // 24 or 32 stages per block

    if (t == 0) {
#pragma unroll
        for (int s = 0; s < NSLOTS; s++) mbar_init(mbar_base + s * 8u, 1u);
        asm volatile("fence.proxy.async.shared::cta;" ::: "memory");
    }
    __syncthreads();

    // ========== PHASE 1: HYBRID — TMA hot rows 0..111 + LDG cold rows 112..128 ==========
    if (warp == 16) {
        // ---- TMA producer (round-10 proven structure: bar.sync-throttled) ----
        int issued = 0;
        const int pro = T < NSLOTS ? T : NSLOTS;
        if (lane == 0)
            for (; issued < pro; issued++) issue_stage(j0, issued, x, w, dyn0, mbar_base);
        issued = pro;
        for (int k = 0; k < T; k++) {
            asm volatile("bar.sync 1, 544;" ::: "memory");
            if (lane == 0 && issued < T) issue_stage(j0, issued, x, w, dyn0, mbar_base);
            issued++;
        }
    } else if (warp < 16) {
        // ---- TMA consumers (512 threads) ----
        float acc0 = 0.f, acc1 = 0.f, acc2 = 0.f, acc3 = 0.f;
        for (int k = 0; k < T; k++) {
            const int slot = k & 3, ph = (k >> 2) & 1;
            mbar_wait(mbar_base + slot * 8u, (uint32_t)ph);
            const float4* b4 = dsm + (size_t)slot * (SLOTB / 16u);
            float4 wv = b4[4 * 512 + t];
            float4 x0 = b4[t];
            float4 x1 = b4[512 + t];
            float4 x2 = b4[2 * 512 + t];
            float4 x3 = b4[3 * 512 + t];
            acc0 = fmaf(x0.x, wv.x, fmaf(x0.y, wv.y, fmaf(x0.z, wv.z, fmaf(x0.w, wv.w, acc0))));
            acc1 = fmaf(x1.x, wv.x, fmaf(x1.y, wv.y, fmaf(x1.z, wv.z, fmaf(x1.w, wv.w, acc1))));
            acc2 = fmaf(x2.x, wv.x, fmaf(x2.y, wv.y, fmaf(x2.z, wv.z, fmaf(x2.w, wv.w, acc2))));
            acc3 = fmaf(x3.x, wv.x, fmaf(x3.y, wv.y, fmaf(x3.z, wv.z, fmaf(x3.w, wv.w, acc3))));
            if ((k & 7) == 7) {
                const int quad = (j0 + (k >> 3)) >> 4;
                float a[4] = {acc0, acc1, acc2, acc3};
#pragma unroll
                for (int i = 0; i < 4; i++) {
                    float s = a[i];
#pragma unroll
                    for (int o = 16; o > 0; o >>= 1) s += __shfl_down_sync(0xffffffffu, s, o);
                    if (lane == 0) sredf[i * 16 + warp] = s;
                }
                asm volatile("bar.sync 2, 512;" ::: "memory");
                if (warp < 4) {
                    float v = (lane < 16) ? sredf[warp * 16 + lane] : 0.f;
#pragma unroll
                    for (int o = 8; o > 0; o >>= 1) v += __shfl_down_sync(0xffffffffu, v, o);
                    int row = 4 * quad + warp;                  // rows 0..111
                    if (lane == 0) atomicAdd(&g_xwa[row * XPAD], v);
                }
                asm volatile("bar.sync 2, 512;" ::: "memory");
                acc0 = acc1 = acc2 = acc3 = 0.f;
            }
            asm volatile("bar.sync 1, 544;" ::: "memory");
        }
    } else {
        // ---- LDG engine: warps 17..31 stream cold rows 112..128 (evict-first) ----
        if (bid < 35) {
            int idx = bid * 480 + (t - 544);
            if (idx < Ee) {
                int cc = ei[Ee + idx];
#pragma unroll
                for (int ch = 0; ch < 3; ch++)
                    atomicAdd(&g_deg[(ch * Nn + cc) * PADS], ea[idx * 3 + ch]);
            }
        }
        const int gw = bid * LWARPS + (warp - 17);
        for (int tile = gw; tile < LTILES; tile += TOTLW) {
            const int row = LROW0 + (tile >> 6), seg = tile & 63;
            const float4* __restrict__ xp =
                (const float4*)x + (size_t)row * (Fdim / 4) + (size_t)seg * 1024 + lane;
            const float4* __restrict__ wp =
                (const float4*)w + (size_t)seg * 1024 + lane;
            float4 acc = make_float4(0.f, 0.f, 0.f, 0.f);
#pragma unroll 4
            for (int i = 0; i < 8; i++) {
                const int o = i * 128;
                float4 a0 = __ldcs(xp + o);
                float4 a1 = __ldcs(xp + o + 32);
                float4 a2 = __ldcs(xp + o + 64);
                float4 a3 = __ldcs(xp + o + 96);
                float4 b0 = __ldg(wp + o);
                float4 b1 = __ldg(wp + o + 32);
                float4 b2 = __ldg(wp + o + 64);
                float4 b3 = __ldg(wp + o + 96);
                acc.x = fmaf(a0.x, b0.x, acc.x); acc.y = fmaf(a0.y, b0.y, acc.y);
                acc.z = fmaf(a0.z, b0.z, acc.z); acc.w = fmaf(a0.w, b0.w, acc.w);
                acc.x = fmaf(a1.x, b1.x, acc.x); acc.y = fmaf(a1.y, b1.y, acc.y);
                acc.z = fmaf(a1.z, b1.z, acc.z); acc.w = fmaf(a1.w, b1.w, acc.w);
                acc.x = fmaf(a2.x, b2.x, acc.x); acc.y = fmaf(a2.y, b2.y, acc.y);
                acc.z = fmaf(a2.z, b2.z, acc.z); acc.w = fmaf(a2.w, b2.w, acc.w);
                acc.x = fmaf(a3.x, b3.x, acc.x); acc.y = fmaf(a3.y, b3.y, acc.y);
                acc.z = fmaf(a3.z, b3.z, acc.z); acc.w = fmaf(a3.w, b3.w, acc.w);
            }
            float s = (acc.x + acc.y) + (acc.z + acc.w);
#pragma unroll
            for (int o = 16; o > 0; o >>= 1) s += __shfl_down_sync(0xffffffffu, s, o);
            if (lane == 0) atomicAdd(&g_xwa[row * XPAD], s);
        }
    }

    gridbar(0, GRID);
    if (bid >= PART2) return;

    // ================= PHASE 2: dinv/xw -> smem, edge agg layer 1 =================
    if (t < Nn) s_xw[t] = __ldcg(&g_xwa[t * XPAD]);
    if (t < NSLOT) {
        float d = __ldcg(&g_deg[t * PADS]) + 1.0f;
        s_dinv[t] = (d > 0.f) ? rsqrtf(d) : 0.f;
    }
    __syncthreads();

    {
        int e = bid * NTHR + t;
        int r = ei[e], c = ei[Ee + e];
        int cp = (bid & (NCOPY - 1)) * NSLOT;
#pragma unroll
        for (int ch = 0; ch < 3; ch++) {
            float ew  = ea[e * 3 + ch];
            float nrm = s_dinv[ch * Nn + r] * ew * s_dinv[ch * Nn + c];
            atomicAdd(&g_h1[(cp + ch * Nn + c) * PADS], nrm * s_xw[r]);
        }
    }

    gridbar(1, PART2);

    // ================= PHASE 3: finalize h1, edge agg layer 2 =================
    const float b1 = g1b[0], W2 = g2W[0];
    if (t < NSLOT) {
        float a1 = 0.f;
#pragma unroll
        for (int c = 0; c < NCOPY; c++) a1 += __ldcg(&g_h1[(c * NSLOT + t) * PADS]);
        float di = s_dinv[t];
        s_h1f[t] = a1 + di * di * s_xw[t % Nn] + b1;
    }
    __syncthreads();

    {
        int e = bid * NTHR + t;
        int r = ei[e], c = ei[Ee + e];
        int cp = (bid & (NCOPY - 1)) * NSLOT;
#pragma unroll
        for (int ch = 0; ch < 3; ch++) {
            float ew  = ea[e * 3 + ch];
            float nrm = s_dinv[ch * Nn + r] * ew * s_dinv[ch * Nn + c];
            atomicAdd(&g_h2[(cp + ch * Nn + c) * PADS], nrm * s_h1f[ch * Nn + r] * W2);
        }
    }
    if (bid == 9 && t < NSLOT) g_deg[t * PADS] = 0.f;
    if (bid == 10 && t < Nn)   g_xwa[t * XPAD] = 0.f;

    gridbar(2, PART2);

    // ================= PHASE 4: cleanup + tail =================
    if (bid != 0) {
        if (bid <= NCOPY) {
            int c = bid - 1;
            if (t < NSLOT) g_h1[(c * NSLOT + t) * PADS] = 0.f;
        }
        return;
    }

    const float b2 = g2b[0];
    if (t < NSLOT) {
        float a2 = 0.f;
#pragma unroll
        for (int c = 0; c < NCOPY; c++) {
            a2 += __ldcg(&g_h2[(c * NSLOT + t) * PADS]);
            g_h2[(c * NSLOT + t) * PADS] = 0.f;
        }
        float di = s_dinv[t];
        s_h2a[t] = a2 + di * di * s_h1f[t] * W2 + b2;
    }
    __syncthreads();

    if (t < NSLOT) {
        int ch = t / Nn, tt = t - ch * Nn;
        float key = s_h2a[ch * Nn + tt];
        float v1  = s_h1f[ch * Nn + tt];
        int rank = 0;
        for (int m = 0; m < Nn; m++) {
            float km = s_h2a[ch * Nn + m];
            rank += (km > key) || (km == key && m < tt);
        }
        z0[ch * Nn + rank] = v1;
        z1[ch * Nn + rank] = key;
    }
    __syncthreads();

    if (t < 3 * 127) {
        int ch = t / 127, tt = t - ch * 127;
#pragma unroll
        for (int o = 0; o < 3; o++) {
            float a = c1b[o];
#pragma unroll
            for (int k = 0; k < 3; k++) {
                a = fmaf(c1w[o * 6 + k],     z0[ch * Nn + tt + k], a);
                a = fmaf(c1w[o * 6 + 3 + k], z1[ch * Nn + tt + k], a);
            }
            c1s[(ch * 3 + o) * 127 + tt] = a;
        }
    }
    __syncthreads();

    if (t < 3 * 125) {
        int ch = t / 125, tt = t - ch * 125;
#pragma unroll
        for (int o = 0; o < 3; o++) {
            const float* p = &c1s[(ch * 3 + o) * 127 + tt];
            p1s[(ch * 3 + o) * 125 + tt] = fmaxf(p[0], fmaxf(p[1], p[2]));
        }
    }
    __syncthreads();

    if (t < 3 * 123) {
        int ch = t / 123, tt = t - ch * 123;
        float a = c2b[0];
#pragma unroll
        for (int in = 0; in < 3; in++)
#pragma unroll
            for (int k = 0; k < 3; k++)
                a = fmaf(c2w[in * 3 + k], p1s[(ch * 3 + in) * 125 + tt + k], a);
        c2s[ch * 123 + tt] = a;
    }
    __syncthreads();

    if (t < 3 * 121) {
        int ch = t / 121, tt = t - ch * 121;
        const float* p = &c2s[ch * 123 + tt];
        allx[ch * 121 + tt] = fmaxf(p[0], fmaxf(p[1], p[2]));
    }
    __syncthreads();

    {
        float a = 0.f;
        for (int i = lane; i < 363; i += 32) a = fmaf(allx[i], f1W[i * 32 + warp], a);
#pragma unroll
        for (int s = 16; s > 0; s >>= 1) a += __shfl_down_sync(0xffffffffu, a, s);
        if (lane == 0 && warp < 32) f1s[warp] = eluf(a + f1b[warp]);
    }
    __syncthreads();
    if (t < 6) {
        float a = f2b[t];
#pragma unroll
        for (int i = 0; i < 32; i++) a = fmaf(f1s[i], f2W[i * 6 + t], a);
        f2s[t] = eluf(a);
    }
    __syncthreads();
    if (t < 2) {
        float a = f3b[t];
#pragma unroll
        for (int i = 0; i < 6; i++) a = fmaf(f2s[i], f3W[i * 2 + t], a);
        out[t] = a;
    }
}

// ---------------- launch ----------------
extern "C" void kernel_launch(void* const* d_in, const int* in_sizes, int n_in,
                              void* d_out, int out_size) {
    const float* x    = (const float*)d_in[0];
    const int*   ei   = (const int*)  d_in[1];
    const float* ea   = (const float*)d_in[2];
    const float* g1W  = (const float*)d_in[3];
    const float* g1b  = (const float*)d_in[4];
    const float* g2W  = (const float*)d_in[5];
    const float* g2b  = (const float*)d_in[6];
    const float* c1w  = (const float*)d_in[7];
    const float* c1b  = (const float*)d_in[8];
    const float* c2w  = (const float*)d_in[9];
    const float* c2b  = (const float*)d_in[10];
    const float* f1W  = (const float*)d_in[11];
    const float* f1b  = (const float*)d_in[12];
    const float* f2W  = (const float*)d_in[13];
    const float* f2b  = (const float*)d_in[14];
    const float* f3W  = (const float*)d_in[15];
    const float* f3b  = (const float*)d_in[16];
    float* out = (float*)d_out;

    static int configured = 0;
    if (!configured) {
        cudaFuncSetAttribute(dgcnn_fused,
                             cudaFuncAttributeMaxDynamicSharedMemorySize,
                             NSLOTS * SLOTB);
        configured = 1;
    }

    dgcnn_fused<<<GRID, NTHR, NSLOTS * SLOTB>>>(x, g1W, ei, ea, g1b, g2W, g2b,
                                                c1w, c1b, c2w, c2b,
                                                f1W, f1b, f2W, f2b, f3W, f3b, out);
}

// round 14
// speedup vs baseline: 1.2888x; 1.2888x over previous
#include <cuda_runtime.h>
#include <math.h>
#include <stdint.h>

// ---------------- problem constants ----------------
#define Nn      129
#define Fdim    262144
#define Ee      16384
#define GRID    148
#define NTHR    1024
#define NCOPY   8
#define PADS    64                      // 256B stride between accumulator slots
#define XPAD    32                      // 128B stride for xw accumulators
#define NSLOT   (3 * Nn)                // 387 (ch,node) slots
#define PART2   16                      // blocks in post-dot phases

// ---- TMA side: rows 64..128 (17 quads, last partially clamped) ----
#define NQUADT  17
#define NJOBST  (NQUADT * 16)           // 272 jobs: (quad, 64KB chunk)
#define STGF    2048                    // floats per row-slice per stage (8KB)
#define STGB    8192u
#define SLOTB   (5u * STGB)             // 40KB per slot
#define NSLOTS  4                       // ring depth -> 160KB dynamic smem

// ---- LDG side: rows 0..63 as 32 row-PAIRS sharing w loads ----
#define NPAIRS  32
#define LTILES  (NPAIRS * 64)           // 2048 tiles (16KB per row per tile)
#define LWARPS  15
#define TOTLW   (GRID * LWARPS)         // 2220 streaming warps

// ---------------- device scratch ----------------
__device__ float    g_xwa[Nn * XPAD];
__device__ float    g_deg[NSLOT * PADS];
__device__ float    g_h1 [NCOPY * NSLOT * PADS];
__device__ float    g_h2 [NCOPY * NSLOT * PADS];
__device__ unsigned g_bar[4];

__device__ __forceinline__ void gridbar(int k, unsigned cnt) {
    __syncthreads();
    __threadfence();
    if (threadIdx.x == 0) {
        unsigned v = atomicAdd(&g_bar[k], 1u);
        unsigned target = (v / cnt) * cnt + cnt;
        while (atomicAdd(&g_bar[k], 0u) < target) __nanosleep(32);
    }
    __syncthreads();
    __threadfence();
}

__device__ __forceinline__ float eluf(float a) { return a > 0.f ? a : expm1f(a); }

__device__ __forceinline__ uint32_t smem_u32(const void* p) {
    uint32_t a;
    asm("{ .reg .u64 tmp; cvta.to.shared.u64 tmp, %1; cvt.u32.u64 %0, tmp; }"
        : "=r"(a) : "l"(p));
    return a;
}
__device__ __forceinline__ void mbar_init(uint32_t mbar, uint32_t cnt) {
    asm volatile("mbarrier.init.shared.b64 [%0], %1;" :: "r"(mbar), "r"(cnt) : "memory");
}
__device__ __forceinline__ void mbar_wait(uint32_t mbar, uint32_t parity) {
    asm volatile(
        "{\n\t.reg .pred P;\n\t"
        "WL_%=:\n\t"
        "mbarrier.try_wait.parity.acquire.cta.shared::cta.b64 P, [%0], %1, 0x989680;\n\t"
        "@P bra WD_%=;\n\tbra WL_%=;\n\tWD_%=:\n\t}"
        :: "r"(mbar), "r"(parity) : "memory");
}

#define BULK(dst, src) \
    asm volatile("cp.async.bulk.shared::cluster.global.mbarrier::complete_tx::bytes [%0], [%1], %2, [%3];" \
                 :: "r"(dst), "l"(src), "r"(STGB), "r"(mbar) : "memory")

// producer: one 40KB stage (4 x-row slices of rows 64+4q.. + w slice)
__device__ __forceinline__ void issue_stage(int j0, int k,
                                            const float* __restrict__ x,
                                            const float* __restrict__ w,
                                            uint32_t dyn0, uint32_t mbar_base) {
    const int job  = j0 + (k >> 3);
    const int s    = k & 7;
    const int quad = job >> 4, chunk = job & 15;
    const size_t base = (size_t)chunk * 16384 + (size_t)s * STGF;
    const int slot = k & 3;
    const uint32_t dst  = dyn0 + (uint32_t)slot * SLOTB;
    const uint32_t mbar = mbar_base + slot * 8u;
    asm volatile("mbarrier.arrive.expect_tx.shared.b64 _, [%0], %1;"
                 :: "r"(mbar), "r"(SLOTB) : "memory");
#pragma unroll
    for (int i = 0; i < 4; i++) {
        int row = 64 + 4 * quad + i;
        if (row > 128) row = 128;               // clamped dup (discarded)
        BULK(dst + (uint32_t)i * STGB, x + (size_t)row * Fdim + base);
    }
    BULK(dst + 4u * STGB, w + base);
}

__global__ void __launch_bounds__(NTHR, 1)
dgcnn_fused(const float* __restrict__ x,   const float* __restrict__ w,
            const int*   __restrict__ ei,  const float* __restrict__ ea,
            const float* __restrict__ g1b, const float* __restrict__ g2W,
            const float* __restrict__ g2b,
            const float* __restrict__ c1w, const float* __restrict__ c1b,
            const float* __restrict__ c2w, const float* __restrict__ c2b,
            const float* __restrict__ f1W, const float* __restrict__ f1b,
            const float* __restrict__ f2W, const float* __restrict__ f2b,
            const float* __restrict__ f3W, const float* __restrict__ f3b,
            float* __restrict__ out) {
    extern __shared__ float4 dsm[];               // 4 x 40KB TMA ring
    __shared__ uint64_t mbarArr[NSLOTS];
    __shared__ float sredf[64];
    __shared__ float s_xw[Nn], s_dinv[NSLOT], s_h1f[NSLOT], s_h2a[NSLOT];
    __shared__ float z0[NSLOT], z1[NSLOT];
    __shared__ float c1s[3 * 3 * 127], p1s[3 * 3 * 125], c2s[3 * 123];
    __shared__ float allx[363], f1s[32], f2s[6];

    const int t    = threadIdx.x;
    const int bid  = blockIdx.x;
    const int lane = t & 31, warp = t >> 5;

    const uint32_t dyn0      = smem_u32(dsm);
    const uint32_t mbar_base = smem_u32(mbarArr);

    const int j0 = (bid * NJOBST) / GRID;
    const int j1 = ((bid + 1) * NJOBST) / GRID;
    const int T  = (j1 - j0) * 8;                 // 8 or 16 stages per block

    if (t == 0) {
#pragma unroll
        for (int s = 0; s < NSLOTS; s++) mbar_init(mbar_base + s * 8u, 1u);
        asm volatile("fence.proxy.async.shared::cta;" ::: "memory");
    }
    __syncthreads();

    // ========== PHASE 1: HYBRID — TMA rows 64..128 + paired-LDG rows 0..63 ==========
    if (warp == 16) {
        // ---- TMA producer (round-10 proven: bar.sync-throttled lockstep) ----
        int issued = 0;
        const int pro = T < NSLOTS ? T : NSLOTS;
        if (lane == 0)
            for (; issued < pro; issued++) issue_stage(j0, issued, x, w, dyn0, mbar_base);
        issued = pro;
        for (int k = 0; k < T; k++) {
            asm volatile("bar.sync 1, 544;" ::: "memory");
            if (lane == 0 && issued < T) issue_stage(j0, issued, x, w, dyn0, mbar_base);
            issued++;
        }
    } else if (warp < 16) {
        // ---- TMA consumers (512 threads) ----
        float acc0 = 0.f, acc1 = 0.f, acc2 = 0.f, acc3 = 0.f;
        for (int k = 0; k < T; k++) {
            const int slot = k & 3, ph = (k >> 2) & 1;
            mbar_wait(mbar_base + slot * 8u, (uint32_t)ph);
            const float4* b4 = dsm + (size_t)slot * (SLOTB / 16u);
            float4 wv = b4[4 * 512 + t];
            float4 x0 = b4[t];
            float4 x1 = b4[512 + t];
            float4 x2 = b4[2 * 512 + t];
            float4 x3 = b4[3 * 512 + t];
            acc0 = fmaf(x0.x, wv.x, fmaf(x0.y, wv.y, fmaf(x0.z, wv.z, fmaf(x0.w, wv.w, acc0))));
            acc1 = fmaf(x1.x, wv.x, fmaf(x1.y, wv.y, fmaf(x1.z, wv.z, fmaf(x1.w, wv.w, acc1))));
            acc2 = fmaf(x2.x, wv.x, fmaf(x2.y, wv.y, fmaf(x2.z, wv.z, fmaf(x2.w, wv.w, acc2))));
            acc3 = fmaf(x3.x, wv.x, fmaf(x3.y, wv.y, fmaf(x3.z, wv.z, fmaf(x3.w, wv.w, acc3))));
            if ((k & 7) == 7) {
                const int quad = (j0 + (k >> 3)) >> 4;
                float a[4] = {acc0, acc1, acc2, acc3};
#pragma unroll
                for (int i = 0; i < 4; i++) {
                    float s = a[i];
#pragma unroll
                    for (int o = 16; o > 0; o >>= 1) s += __shfl_down_sync(0xffffffffu, s, o);
                    if (lane == 0) sredf[i * 16 + warp] = s;
                }
                asm volatile("bar.sync 2, 512;" ::: "memory");
                if (warp < 4) {
                    float v = (lane < 16) ? sredf[warp * 16 + lane] : 0.f;
#pragma unroll
                    for (int o = 8; o > 0; o >>= 1) v += __shfl_down_sync(0xffffffffu, v, o);
                    int row = 64 + 4 * quad + warp;
                    if (lane == 0 && row <= 128) atomicAdd(&g_xwa[row * XPAD], v);
                }
                asm volatile("bar.sync 2, 512;" ::: "memory");
                acc0 = acc1 = acc2 = acc3 = 0.f;
            }
            asm volatile("bar.sync 1, 544;" ::: "memory");
        }
    } else {
        // ---- paired-LDG engine: warps 17..31 stream rows 0..63, 2 rows share w ----
        if (bid < 35) {
            int idx = bid * 480 + (t - 544);
            if (idx < Ee) {
                int cc = ei[Ee + idx];
#pragma unroll
                for (int ch = 0; ch < 3; ch++)
                    atomicAdd(&g_deg[(ch * Nn + cc) * PADS], ea[idx * 3 + ch]);
            }
        }
        const int gw = bid * LWARPS + (warp - 17);
        for (int tile = gw; tile < LTILES; tile += TOTLW) {
            const int pr = tile >> 6, seg = tile & 63;     // rows 2pr, 2pr+1
            const float4* __restrict__ xA =
                (const float4*)x + (size_t)(2 * pr) * (Fdim / 4) + (size_t)seg * 1024 + lane;
            const float4* __restrict__ xB = xA + (Fdim / 4);
            const float4* __restrict__ wp =
                (const float4*)w + (size_t)seg * 1024 + lane;
            float4 aA = make_float4(0.f, 0.f, 0.f, 0.f);
            float4 aB = make_float4(0.f, 0.f, 0.f, 0.f);
#pragma unroll 4
            for (int i = 0; i < 16; i++) {
                const int o = i * 64;
                float4 a0 = __ldcs(xA + o);
                float4 a1 = __ldcs(xA + o + 32);
                float4 b0 = __ldcs(xB + o);
                float4 b1 = __ldcs(xB + o + 32);
                float4 w0 = __ldg(wp + o);
                float4 w1 = __ldg(wp + o + 32);
                aA.x = fmaf(a0.x, w0.x, aA.x); aA.y = fmaf(a0.y, w0.y, aA.y);
                aA.z = fmaf(a0.z, w0.z, aA.z); aA.w = fmaf(a0.w, w0.w, aA.w);
                aA.x = fmaf(a1.x, w1.x, aA.x); aA.y = fmaf(a1.y, w1.y, aA.y);
                aA.z = fmaf(a1.z, w1.z, aA.z); aA.w = fmaf(a1.w, w1.w, aA.w);
                aB.x = fmaf(b0.x, w0.x, aB.x); aB.y = fmaf(b0.y, w0.y, aB.y);
                aB.z = fmaf(b0.z, w0.z, aB.z); aB.w = fmaf(b0.w, w0.w, aB.w);
                aB.x = fmaf(b1.x, w1.x, aB.x); aB.y = fmaf(b1.y, w1.y, aB.y);
                aB.z = fmaf(b1.z, w1.z, aB.z); aB.w = fmaf(b1.w, w1.w, aB.w);
            }
            float sA = (aA.x + aA.y) + (aA.z + aA.w);
            float sB = (aB.x + aB.y) + (aB.z + aB.w);
#pragma unroll
            for (int o = 16; o > 0; o >>= 1) {
                sA += __shfl_down_sync(0xffffffffu, sA, o);
                sB += __shfl_down_sync(0xffffffffu, sB, o);
            }
            if (lane == 0) {
                atomicAdd(&g_xwa[(2 * pr)     * XPAD], sA);
                atomicAdd(&g_xwa[(2 * pr + 1) * XPAD], sB);
            }
        }
    }

    gridbar(0, GRID);
    if (bid >= PART2) return;

    // ================= PHASE 2: dinv/xw -> smem, edge agg layer 1 =================
    if (t < Nn) s_xw[t] = __ldcg(&g_xwa[t * XPAD]);
    if (t < NSLOT) {
        float d = __ldcg(&g_deg[t * PADS]) + 1.0f;
        s_dinv[t] = (d > 0.f) ? rsqrtf(d) : 0.f;
    }
    __syncthreads();

    {
        int e = bid * NTHR + t;
        int r = ei[e], c = ei[Ee + e];
        int cp = (bid & (NCOPY - 1)) * NSLOT;
#pragma unroll
        for (int ch = 0; ch < 3; ch++) {
            float ew  = ea[e * 3 + ch];
            float nrm = s_dinv[ch * Nn + r] * ew * s_dinv[ch * Nn + c];
            atomicAdd(&g_h1[(cp + ch * Nn + c) * PADS], nrm * s_xw[r]);
        }
    }

    gridbar(1, PART2);

    // ================= PHASE 3: finalize h1, edge agg layer 2 =================
    const float b1 = g1b[0], W2 = g2W[0];
    if (t < NSLOT) {
        float a1 = 0.f;
#pragma unroll
        for (int c = 0; c < NCOPY; c++) a1 += __ldcg(&g_h1[(c * NSLOT + t) * PADS]);
        float di = s_dinv[t];
        s_h1f[t] = a1 + di * di * s_xw[t % Nn] + b1;
    }
    __syncthreads();

    {
        int e = bid * NTHR + t;
        int r = ei[e], c = ei[Ee + e];
        int cp = (bid & (NCOPY - 1)) * NSLOT;
#pragma unroll
        for (int ch = 0; ch < 3; ch++) {
            float ew  = ea[e * 3 + ch];
            float nrm = s_dinv[ch * Nn + r] * ew * s_dinv[ch * Nn + c];
            atomicAdd(&g_h2[(cp + ch * Nn + c) * PADS], nrm * s_h1f[ch * Nn + r] * W2);
        }
    }
    if (bid == 9 && t < NSLOT) g_deg[t * PADS] = 0.f;
    if (bid == 10 && t < Nn)   g_xwa[t * XPAD] = 0.f;

    gridbar(2, PART2);

    // ================= PHASE 4: cleanup + tail =================
    if (bid != 0) {
        if (bid <= NCOPY) {
            int c = bid - 1;
            if (t < NSLOT) g_h1[(c * NSLOT + t) * PADS] = 0.f;
        }
        return;
    }

    const float b2 = g2b[0];
    if (t < NSLOT) {
        float a2 = 0.f;
#pragma unroll
        for (int c = 0; c < NCOPY; c++) {
            a2 += __ldcg(&g_h2[(c * NSLOT + t) * PADS]);
            g_h2[(c * NSLOT + t) * PADS] = 0.f;
        }
        float di = s_dinv[t];
        s_h2a[t] = a2 + di * di * s_h1f[t] * W2 + b2;
    }
    __syncthreads();

    if (t < NSLOT) {
        int ch = t / Nn, tt = t - ch * Nn;
        float key = s_h2a[ch * Nn + tt];
        float v1  = s_h1f[ch * Nn + tt];
        int rank = 0;
        for (int m = 0; m < Nn; m++) {
            float km = s_h2a[ch * Nn + m];
            rank += (km > key) || (km == key && m < tt);
        }
        z0[ch * Nn + rank] = v1;
        z1[ch * Nn + rank] = key;
    }
    __syncthreads();

    if (t < 3 * 127) {
        int ch = t / 127, tt = t - ch * 127;
#pragma unroll
        for (int o = 0; o < 3; o++) {
            float a = c1b[o];
#pragma unroll
            for (int k = 0; k < 3; k++) {
                a = fmaf(c1w[o * 6 + k],     z0[ch * Nn + tt + k], a);
                a = fmaf(c1w[o * 6 + 3 + k], z1[ch * Nn + tt + k], a);
            }
            c1s[(ch * 3 + o) * 127 + tt] = a;
        }
    }
    __syncthreads();

    if (t < 3 * 125) {
        int ch = t / 125, tt = t - ch * 125;
#pragma unroll
        for (int o = 0; o < 3; o++) {
            const float* p = &c1s[(ch * 3 + o) * 127 + tt];
            p1s[(ch * 3 + o) * 125 + tt] = fmaxf(p[0], fmaxf(p[1], p[2]));
        }
    }
    __syncthreads();

    if (t < 3 * 123) {
        int ch = t / 123, tt = t - ch * 123;
        float a = c2b[0];
#pragma unroll
        for (int in = 0; in < 3; in++)
#pragma unroll
            for (int k = 0; k < 3; k++)
                a = fmaf(c2w[in * 3 + k], p1s[(ch * 3 + in) * 125 + tt + k], a);
        c2s[ch * 123 + tt] = a;
    }
    __syncthreads();

    if (t < 3 * 121) {
        int ch = t / 121, tt = t - ch * 121;
        const float* p = &c2s[ch * 123 + tt];
        allx[ch * 121 + tt] = fmaxf(p[0], fmaxf(p[1], p[2]));
    }
    __syncthreads();

    {
        float a = 0.f;
        for (int i = lane; i < 363; i += 32) a = fmaf(allx[i], f1W[i * 32 + warp], a);
#pragma unroll
        for (int s = 16; s > 0; s >>= 1) a += __shfl_down_sync(0xffffffffu, a, s);
        if (lane == 0 && warp < 32) f1s[warp] = eluf(a + f1b[warp]);
    }
    __syncthreads();
    if (t < 6) {
        float a = f2b[t];
#pragma unroll
        for (int i = 0; i < 32; i++) a = fmaf(f1s[i], f2W[i * 6 + t], a);
        f2s[t] = eluf(a);
    }
    __syncthreads();
    if (t < 2) {
        float a = f3b[t];
#pragma unroll
        for (int i = 0; i < 6; i++) a = fmaf(f2s[i], f3W[i * 2 + t], a);
        out[t] = a;
    }
}

// ---------------- launch ----------------
extern "C" void kernel_launch(void* const* d_in, const int* in_sizes, int n_in,
                              void* d_out, int out_size) {
    const float* x    = (const float*)d_in[0];
    const int*   ei   = (const int*)  d_in[1];
    const float* ea   = (const float*)d_in[2];
    const float* g1W  = (const float*)d_in[3];
    const float* g1b  = (const float*)d_in[4];
    const float* g2W  = (const float*)d_in[5];
    const float* g2b  = (const float*)d_in[6];
    const float* c1w  = (const float*)d_in[7];
    const float* c1b  = (const float*)d_in[8];
    const float* c2w  = (const float*)d_in[9];
    const float* c2b  = (const float*)d_in[10];
    const float* f1W  = (const float*)d_in[11];
    const float* f1b  = (const float*)d_in[12];
    const float* f2W  = (const float*)d_in[13];
    const float* f2b  = (const float*)d_in[14];
    const float* f3W  = (const float*)d_in[15];
    const float* f3b  = (const float*)d_in[16];
    float* out = (float*)d_out;

    static int configured = 0;
    if (!configured) {
        cudaFuncSetAttribute(dgcnn_fused,
                             cudaFuncAttributeMaxDynamicSharedMemorySize,
                             NSLOTS * SLOTB);
        configured = 1;
    }

    dgcnn_fused<<<GRID, NTHR, NSLOTS * SLOTB>>>(x, g1W, ei, ea, g1b, g2W, g2b,
                                                c1w, c1b, c2w, c2b,
                                                f1W, f1b, f2W, f2b, f3W, f3b, out);
}